// round 7
// baseline (speedup 1.0000x reference)
#include <cuda_runtime.h>

#define NBLK 128
#define NTHR 384
#define B_ 2
#define M_ 768
#define N_ 512
#define MN_ (M_*N_)
#define AW (1.0f/768.0f)
#define BW (1.0f/512.0f)
#define EPSI 20.0f
#define RPB 12            // rows per block: 128*12 = 1536 = B*M
#define AS_STRIDE 98      // padded 96+2
#define AS_BUF (16*AS_STRIDE)
#define BS_BUF (16*64)

typedef unsigned long long ull;

// ---------------- device scratch ----------------
__device__ float g_P [B_*MN_];
__device__ float g_Km[B_*MN_];
__device__ float g_T [B_*MN_];
__device__ float g_rm[B_*M_];
__device__ float g_t1[B_*M_];
__device__ float g_t2[B_*N_];
__device__ float g_csum[3][B_*N_];   // triple-buffered atomic column sums
__device__ float g_cp[128];
__device__ float g_acc[4];
__device__ unsigned g_bar[64];       // [0] batch0 counter, [32] batch1

__global__ void reset_kernel() { g_bar[0] = 0u; g_bar[32] = 0u; }

// ---------------- barrier: release-arrive, fast relaxed poll ----------------
__device__ __forceinline__ void gsync(unsigned &gen, unsigned* ctr) {
    ++gen;
    __syncthreads();
    if (threadIdx.x == 0) {
        asm volatile("red.release.gpu.global.add.u32 [%0], %1;"
                     :: "l"(ctr), "r"(1u) : "memory");
        unsigned target = gen * 64u;
        unsigned v0, v1, v2, v3;
        while (true) {
            asm volatile("ld.relaxed.gpu.global.b32 %0, [%4];\n\t"
                         "ld.relaxed.gpu.global.b32 %1, [%4];\n\t"
                         "ld.relaxed.gpu.global.b32 %2, [%4];\n\t"
                         "ld.relaxed.gpu.global.b32 %3, [%4];"
                         : "=r"(v0), "=r"(v1), "=r"(v2), "=r"(v3) : "l"(ctr));
            if (v3 >= target || v2 >= target || v1 >= target || v0 >= target) break;
        }
        asm volatile("fence.acq_rel.gpu;" ::: "memory");
    }
    __syncthreads();
}

// ---------------- packed f32x2 helpers ----------------
__device__ __forceinline__ void fma2(ull &d, ull a, ull b) {
    asm("fma.rn.f32x2 %0, %1, %2, %0;" : "+l"(d) : "l"(a), "l"(b));
}
__device__ __forceinline__ ull splat(float x) {
    ull r; asm("mov.b64 %0, {%1, %1};" : "=l"(r) : "f"(x)); return r;
}

// ---------------- GEMM tile 96x64 (128 tiles), 384 thr, micro 4x4 ----------
// MODE 0: g_T  = g_P @ D2
// MODE 1: g_Km = exp((2*(D1@g_T) - t1 - t2)*EPSI)
// MODE 2: g_cp[tile] = sum((D1@g_P)_tile .* g_T_tile)
template<int MODE>
__device__ void gemm_tile(int tile, const float* __restrict__ D1,
                          const float* __restrict__ D2,
                          float* As, float* Bs, float* red) {
    const int Kd  = (MODE == 0) ? N_ : M_;
    const int lda = (MODE == 0) ? N_ : M_;
    int b = tile >> 6;
    int r = tile & 63;
    int row0 = (r >> 3) * 96;
    int col0 = (r & 7) * 64;
    const float* A  = (MODE == 0) ? (g_P + (size_t)b*MN_) : (D1 + (size_t)b*M_*M_);
    const float* Bm = (MODE == 0) ? (D2 + (size_t)b*(size_t)N_*N_)
                    : (MODE == 1) ? (g_T + (size_t)b*MN_)
                                  : (g_P + (size_t)b*MN_);
    int tid = threadIdx.x;
    int tx = tid & 15, ty = tid >> 4;

    int lr = tid >> 2;
    int lk = (tid & 3) * 4;
    const float* ApL = A + (size_t)(row0 + lr)*lda + lk;
    int brow = tid >> 4, bq = tid & 15;
    const float* BpL = Bm + (size_t)brow*N_ + col0 + bq*4;

    ull acc[2][4];
    #pragma unroll
    for (int i = 0; i < 2; i++)
        #pragma unroll
        for (int j = 0; j < 4; j++) acc[i][j] = 0ull;

    float4 pa = *(const float4*)(ApL);
    float4 pb;
    if (tid < 256) pb = *(const float4*)(BpL);

    int buf = 0;
    for (int k0 = 0; k0 < Kd; k0 += 16) {
        float* Asb = As + buf*AS_BUF;
        float* Bsb = Bs + buf*BS_BUF;
        Asb[(lk+0)*AS_STRIDE + lr] = pa.x;
        Asb[(lk+1)*AS_STRIDE + lr] = pa.y;
        Asb[(lk+2)*AS_STRIDE + lr] = pa.z;
        Asb[(lk+3)*AS_STRIDE + lr] = pa.w;
        if (tid < 256) *(float4*)&Bsb[brow*64 + bq*4] = pb;
        if (k0 + 16 < Kd) {
            pa = *(const float4*)(ApL + k0 + 16);
            if (tid < 256) pb = *(const float4*)(BpL + (size_t)(k0+16)*N_);
        }
        __syncthreads();
        #pragma unroll
        for (int k = 0; k < 16; k++) {
            const float* ap = Asb + k*AS_STRIDE + ty*4;
            ull a01 = *(const ull*)(ap);
            ull a23 = *(const ull*)(ap + 2);
            float4 b4 = *(const float4*)&Bsb[k*64 + tx*4];
            ull b0 = splat(b4.x), b1 = splat(b4.y), b2 = splat(b4.z), b3 = splat(b4.w);
            fma2(acc[0][0], a01, b0); fma2(acc[0][1], a01, b1);
            fma2(acc[0][2], a01, b2); fma2(acc[0][3], a01, b3);
            fma2(acc[1][0], a23, b0); fma2(acc[1][1], a23, b1);
            fma2(acc[1][2], a23, b2); fma2(acc[1][3], a23, b3);
        }
        buf ^= 1;
    }

    float cS[4][4];
    #pragma unroll
    for (int p = 0; p < 2; p++)
        #pragma unroll
        for (int j = 0; j < 4; j++) {
            union { ull u; float f[2]; } cv; cv.u = acc[p][j];
            cS[2*p][j]   = cv.f[0];
            cS[2*p+1][j] = cv.f[1];
        }

    if (MODE == 0) {
        float* Cb = g_T + (size_t)b*MN_;
        #pragma unroll
        for (int rr = 0; rr < 4; rr++) {
            int row = row0 + ty*4 + rr;
            float4 v = make_float4(cS[rr][0], cS[rr][1], cS[rr][2], cS[rr][3]);
            *(float4*)(Cb + (size_t)row*N_ + col0 + tx*4) = v;
        }
    } else if (MODE == 1) {
        float* Cb = g_Km + (size_t)b*MN_;
        const float* t1b = g_t1 + b*M_;
        const float* t2b = g_t2 + b*N_;
        float t20 = t2b[col0+tx*4+0], t21 = t2b[col0+tx*4+1];
        float t22 = t2b[col0+tx*4+2], t23 = t2b[col0+tx*4+3];
        #pragma unroll
        for (int rr = 0; rr < 4; rr++) {
            int row = row0 + ty*4 + rr;
            float t1v = t1b[row];
            float4 v;
            v.x = __expf((2.0f*cS[rr][0] - t1v - t20) * EPSI);
            v.y = __expf((2.0f*cS[rr][1] - t1v - t21) * EPSI);
            v.z = __expf((2.0f*cS[rr][2] - t1v - t22) * EPSI);
            v.w = __expf((2.0f*cS[rr][3] - t1v - t23) * EPSI);
            *(float4*)(Cb + (size_t)row*N_ + col0 + tx*4) = v;
        }
    } else {
        const float* Tb = g_T + (size_t)b*MN_;
        float local = 0.f;
        #pragma unroll
        for (int rr = 0; rr < 4; rr++) {
            int row = row0 + ty*4 + rr;
            float4 tv = *(const float4*)(Tb + (size_t)row*N_ + col0 + tx*4);
            local += cS[rr][0]*tv.x + cS[rr][1]*tv.y + cS[rr][2]*tv.z + cS[rr][3]*tv.w;
        }
        red[tid] = local;
        __syncthreads();
        if (tid < 128) red[tid] += red[tid + 128] + red[tid + 256];
        __syncthreads();
        for (int st = 64; st; st >>= 1) {
            if (tid < st) red[tid] += red[tid + st];
            __syncthreads();
        }
        if (!tid) g_cp[tile] = red[0];
    }
}

// ---------------- t1 = (D1.^2) @ rm  (warp per row, 12 warps) --------------
__device__ void sqmv_t1(const float* __restrict__ D1, int bid, int wid, int lane) {
    int fi = bid*RPB + wid;
    int b2 = fi >= M_;
    int i  = fi - b2*M_;
    const float4* row = (const float4*)(D1 + ((size_t)b2*M_ + i)*M_);
    const float4* rmb = (const float4*)(g_rm + b2*M_);
    float s = 0.f;
    for (int q = lane; q < 192; q += 32) {
        float4 v  = row[q];
        float4 r4 = rmb[q];
        s += v.x*v.x*r4.x + v.y*v.y*r4.y + v.z*v.z*r4.z + v.w*v.w*r4.w;
    }
    #pragma unroll
    for (int o = 16; o; o >>= 1) s += __shfl_xor_sync(0xffffffffu, s, o);
    if (!lane) g_t1[fi] = s;
}

// ---------------- persistent mega-kernel ----------------
__global__ void __launch_bounds__(NTHR)
gw_kernel(const float* __restrict__ D1, const float* __restrict__ D2,
          float* __restrict__ out, int out_size) {
    __shared__ float sKs[RPB*N_];        // 24 KB K-row cache
    __shared__ float As[2*AS_BUF];
    __shared__ float Bs[2*BS_BUF];
    __shared__ float tS[N_];
    __shared__ float sRed[NTHR];
    __shared__ float sLoc[RPB];

    int bid = blockIdx.x, tid = threadIdx.x;
    int wid = tid >> 5, lane = tid & 31;
    unsigned gen = 0;
    int bb = bid >> 6;                          // batch (64 blocks each)
    int lid6 = bid & 63;
    unsigned* ctr = &g_bar[bb*32];
    size_t rowbase = (size_t)bid * (RPB*N_);

    // ---------- Phase I: init P, rm, t2, csum[0] ----------
    for (int idx = tid; idx < RPB*N_; idx += NTHR) g_P[rowbase + idx] = AW*BW;
    if (tid < RPB) g_rm[bid*RPB + tid] = AW;
    if (wid < 8) {
        int gw2 = bid*8 + wid;
        int b2 = gw2 >> 9, j = gw2 & 511;
        const float4* row = (const float4*)(D2 + ((size_t)b2*N_ + j)*N_);
        float s = 0.f;
        for (int q = lane; q < 128; q += 32) {
            float4 v = row[q];
            s += v.x*v.x + v.y*v.y + v.z*v.z + v.w*v.w;
        }
        #pragma unroll
        for (int o = 16; o; o >>= 1) s += __shfl_xor_sync(0xffffffffu, s, o);
        if (!lane) g_t2[gw2] = BW * s;
    }
    if (lid6 == 0)
        for (int idx = tid; idx < N_; idx += NTHR) g_csum[0][bb*N_ + idx] = 0.f;
    gsync(gen, ctr);

    int git = 0;
    for (int outer = 0; outer < 10; outer++) {
        // Phase A: T = P@D2 (1 tile/block) + t1 sqmv
        gemm_tile<0>(bid, D1, D2, As, Bs, sRed);
        sqmv_t1(D1, bid, wid, lane);
        gsync(gen, ctr);

        // Phase B: Km = exp(...)
        gemm_tile<1>(bid, D1, D2, As, Bs, sRed);
        gsync(gen, ctr);

        // Sinkhorn: 20 iterations, 1 barrier each
        for (int it = 0; it < 20; it++, git++) {
            if (it == 0) {
                const float4* src = (const float4*)(g_Km + rowbase);
                float4* dst = (float4*)sKs;
                for (int idx = tid; idx < RPB*N_/4; idx += NTHR) dst[idx] = src[idx];
                __syncthreads();
            }
            // u-dot: warp wid handles row wid
            {
                float s = 0.f;
                if (it == 0) {
                    for (int q = lane; q < 128; q += 32) {
                        float4 v = *(const float4*)&sKs[wid*N_ + q*4];
                        s += v.x + v.y + v.z + v.w;
                    }
                } else {
                    for (int q = lane; q < 128; q += 32) {
                        float4 v  = *(const float4*)&sKs[wid*N_ + q*4];
                        float4 t4 = *(const float4*)&tS[q*4];
                        s += v.x*t4.x + v.y*t4.y + v.z*t4.z + v.w*t4.w;
                    }
                }
                #pragma unroll
                for (int o = 16; o; o >>= 1) s += __shfl_xor_sync(0xffffffffu, s, o);
                if (!lane) sLoc[wid] = __fdividef(AW, s);
            }
            __syncthreads();
            // column partials (float4 per thread, tid<128) -> ONE red.v4 each
            {
                int p = git % 3;
                if (tid < 128) {
                    float ax = 0.f, ay = 0.f, az = 0.f, aw = 0.f;
                    #pragma unroll
                    for (int rr = 0; rr < RPB; rr++) {
                        float4 v = *(const float4*)&sKs[rr*N_ + tid*4];
                        float sv = sLoc[rr];
                        ax += v.x*sv; ay += v.y*sv; az += v.z*sv; aw += v.w*sv;
                    }
                    asm volatile("red.global.add.v4.f32 [%0], {%1,%2,%3,%4};"
                                 :: "l"(&g_csum[p][bb*N_ + tid*4]),
                                    "f"(ax), "f"(ay), "f"(az), "f"(aw) : "memory");
                }
                int pn = (p + 1 == 3) ? 0 : p + 1;
                if (tid >= 128 && tid < 136)
                    g_csum[pn][bb*N_ + lid6*8 + (tid - 128)] = 0.f;
            }
            gsync(gen, ctr);
            // t recompute (vectorized, 128 threads)
            {
                int p = git % 3;
                if (tid < 128) {
                    float4 c = *(const float4*)&g_csum[p][bb*N_ + tid*4];
                    float4 t4;
                    t4.x = __fdividef(BW, c.x);
                    t4.y = __fdividef(BW, c.y);
                    t4.z = __fdividef(BW, c.z);
                    t4.w = __fdividef(BW, c.w);
                    *(float4*)&tS[tid*4] = t4;
                }
            }
            __syncthreads();
        }

        // P update + row masses (warp per row)
        {
            float s = 0.f;
            for (int q = lane; q < 128; q += 32) {
                float4 v  = *(const float4*)&sKs[wid*N_ + q*4];
                float4 t4 = *(const float4*)&tS[q*4];
                s += v.x*t4.x + v.y*t4.y + v.z*t4.z + v.w*t4.w;
            }
            #pragma unroll
            for (int o = 16; o; o >>= 1) s += __shfl_xor_sync(0xffffffffu, s, o);
            if (!lane) g_rm[bid*RPB + wid] = sLoc[wid] * s;
        }
        for (int c = tid; c < RPB*N_; c += NTHR) {
            int rr = c >> 9, j = c & 511;
            g_P[rowbase + c] = sLoc[rr] * sKs[c] * tS[j];
        }
        gsync(gen, ctr);
    }

    // ---------- Final cost ----------
    gemm_tile<0>(bid, D1, D2, As, Bs, sRed);
    sqmv_t1(D1, bid, wid, lane);
    gsync(gen, ctr);

    gemm_tile<2>(bid, D1, D2, As, Bs, sRed);
    __syncthreads();
    if (lid6 == 0) {                       // blocks 0, 64: rm . t1
        float s = 0.f;
        for (int i = tid; i < M_; i += NTHR) s += g_rm[bb*M_ + i] * g_t1[bb*M_ + i];
        sRed[tid] = s;
        __syncthreads();
        if (tid < 128) sRed[tid] += sRed[tid + 128] + sRed[tid + 256];
        __syncthreads();
        for (int st = 64; st; st >>= 1) {
            if (tid < st) sRed[tid] += sRed[tid + st];
            __syncthreads();
        }
        if (!tid) g_acc[bb] = sRed[0];
    } else if (lid6 == 1) {                // blocks 1, 65: BW * sum t2
        float s = 0.f;
        for (int j = tid; j < N_; j += NTHR) s += g_t2[bb*N_ + j];
        sRed[tid] = s;
        __syncthreads();
        if (tid < 128) sRed[tid] += sRed[tid + 128] + sRed[tid + 256];
        __syncthreads();
        for (int st = 64; st; st >>= 1) {
            if (tid < st) sRed[tid] += sRed[tid + st];
            __syncthreads();
        }
        if (!tid) g_acc[2 + bb] = BW * sRed[0];
    }
    gsync(gen, ctr);

    // outputs
    if (lid6 == 0 && tid == 0) {
        float cr = 0.f;
        for (int t = 0; t < 64; t++) cr += g_cp[bb*64 + t];
        out[bb] = g_acc[bb] + g_acc[2 + bb] - 2.0f*cr;
    }
    if (out_size > 2) {
        const float2* src = (const float2*)(g_P + rowbase);
        float2* dst = (float2*)(out + 2 + rowbase);
        for (int idx = tid; idx < RPB*N_/2; idx += NTHR) dst[idx] = src[idx];
    }
}

// ---------------- host driver ----------------
extern "C" void kernel_launch(void* const* d_in, const int* in_sizes, int n_in,
                              void* d_out, int out_size) {
    const float* D1 = (const float*)d_in[0];
    const float* D2 = (const float*)d_in[1];
    if (n_in >= 2 && in_sizes[0] == B_*N_*N_ && in_sizes[1] == B_*M_*M_) {
        const float* tmp = D1; D1 = D2; D2 = tmp;
    }
    float* out = (float*)d_out;

    reset_kernel<<<1, 1>>>();
    gw_kernel<<<NBLK, NTHR>>>(D1, D2, out, out_size);
}

// round 8
// speedup vs baseline: 1.0686x; 1.0686x over previous
#include <cuda_runtime.h>

#define NBLK 128
#define NTHR 384
#define B_ 2
#define M_ 768
#define N_ 512
#define MN_ (M_*N_)
#define AW (1.0f/768.0f)
#define BW (1.0f/512.0f)
#define EPSI 20.0f
#define RPB 12            // rows per block: 128*12 = 1536 = B*M
#define AS_STRIDE 98      // padded 96+2
#define AS_BUF (16*AS_STRIDE)
#define BS_BUF (16*64)

typedef unsigned long long ull;

// ---------------- device scratch ----------------
__device__ float g_P [B_*MN_];
__device__ float g_Km[B_*MN_];
__device__ float g_T [B_*MN_];
__device__ float g_rm[B_*M_];
__device__ float g_t1[B_*M_];
__device__ float g_t2[B_*N_];
__device__ float g_csum[3][B_*N_];   // triple-buffered atomic column sums
__device__ float g_cp[128];
__device__ float g_acc[4];
__device__ unsigned g_bar[64];       // [0] batch0 counter, [32] batch1

__global__ void reset_kernel() { g_bar[0] = 0u; g_bar[32] = 0u; }

// ------- per-batch count barrier (R5 version): release-arrive, acquire-poll --
__device__ __forceinline__ void gsync(unsigned &gen, unsigned* ctr) {
    ++gen;
    __syncthreads();
    if (threadIdx.x == 0) {
        asm volatile("red.release.gpu.global.add.u32 [%0], %1;"
                     :: "l"(ctr), "r"(1u) : "memory");
        unsigned target = gen * 64u;
        unsigned v;
        do {
            asm volatile("ld.acquire.gpu.global.b32 %0, [%1];"
                         : "=r"(v) : "l"(ctr) : "memory");
        } while (v < target);
    }
    __syncthreads();
}

// ---------------- packed f32x2 helpers ----------------
__device__ __forceinline__ void fma2(ull &d, ull a, ull b) {
    asm("fma.rn.f32x2 %0, %1, %2, %0;" : "+l"(d) : "l"(a), "l"(b));
}
__device__ __forceinline__ ull splat(float x) {
    ull r; asm("mov.b64 %0, {%1, %1};" : "=l"(r) : "f"(x)); return r;
}

// ---------------- GEMM tile 96x64 (128 tiles), 384 thr, micro 4x4 ----------
// MODE 0: g_T  = g_P @ D2
// MODE 1: g_Km = exp((2*(D1@g_T) - t1 - t2)*EPSI)
// MODE 2: g_cp[tile] = sum((D1@g_P)_tile .* g_T_tile)
template<int MODE>
__device__ void gemm_tile(int tile, const float* __restrict__ D1,
                          const float* __restrict__ D2,
                          float* As, float* Bs, float* red) {
    const int Kd  = (MODE == 0) ? N_ : M_;
    const int lda = (MODE == 0) ? N_ : M_;
    int b = tile >> 6;
    int r = tile & 63;
    int row0 = (r >> 3) * 96;
    int col0 = (r & 7) * 64;
    const float* A  = (MODE == 0) ? (g_P + (size_t)b*MN_) : (D1 + (size_t)b*M_*M_);
    const float* Bm = (MODE == 0) ? (D2 + (size_t)b*(size_t)N_*N_)
                    : (MODE == 1) ? (g_T + (size_t)b*MN_)
                                  : (g_P + (size_t)b*MN_);
    int tid = threadIdx.x;
    int tx = tid & 15, ty = tid >> 4;

    int lr = tid >> 2;
    int lk = (tid & 3) * 4;
    const float* ApL = A + (size_t)(row0 + lr)*lda + lk;
    int brow = tid >> 4, bq = tid & 15;
    const float* BpL = Bm + (size_t)brow*N_ + col0 + bq*4;

    ull acc[2][4];
    #pragma unroll
    for (int i = 0; i < 2; i++)
        #pragma unroll
        for (int j = 0; j < 4; j++) acc[i][j] = 0ull;

    float4 pa = *(const float4*)(ApL);
    float4 pb;
    if (tid < 256) pb = *(const float4*)(BpL);

    int buf = 0;
    for (int k0 = 0; k0 < Kd; k0 += 16) {
        float* Asb = As + buf*AS_BUF;
        float* Bsb = Bs + buf*BS_BUF;
        Asb[(lk+0)*AS_STRIDE + lr] = pa.x;
        Asb[(lk+1)*AS_STRIDE + lr] = pa.y;
        Asb[(lk+2)*AS_STRIDE + lr] = pa.z;
        Asb[(lk+3)*AS_STRIDE + lr] = pa.w;
        if (tid < 256) *(float4*)&Bsb[brow*64 + bq*4] = pb;
        if (k0 + 16 < Kd) {
            pa = *(const float4*)(ApL + k0 + 16);
            if (tid < 256) pb = *(const float4*)(BpL + (size_t)(k0+16)*N_);
        }
        __syncthreads();
        #pragma unroll
        for (int k = 0; k < 16; k++) {
            const float* ap = Asb + k*AS_STRIDE + ty*4;
            ull a01 = *(const ull*)(ap);
            ull a23 = *(const ull*)(ap + 2);
            float4 b4 = *(const float4*)&Bsb[k*64 + tx*4];
            ull b0 = splat(b4.x), b1 = splat(b4.y), b2 = splat(b4.z), b3 = splat(b4.w);
            fma2(acc[0][0], a01, b0); fma2(acc[0][1], a01, b1);
            fma2(acc[0][2], a01, b2); fma2(acc[0][3], a01, b3);
            fma2(acc[1][0], a23, b0); fma2(acc[1][1], a23, b1);
            fma2(acc[1][2], a23, b2); fma2(acc[1][3], a23, b3);
        }
        buf ^= 1;
    }

    float cS[4][4];
    #pragma unroll
    for (int p = 0; p < 2; p++)
        #pragma unroll
        for (int j = 0; j < 4; j++) {
            union { ull u; float f[2]; } cv; cv.u = acc[p][j];
            cS[2*p][j]   = cv.f[0];
            cS[2*p+1][j] = cv.f[1];
        }

    if (MODE == 0) {
        float* Cb = g_T + (size_t)b*MN_;
        #pragma unroll
        for (int rr = 0; rr < 4; rr++) {
            int row = row0 + ty*4 + rr;
            float4 v = make_float4(cS[rr][0], cS[rr][1], cS[rr][2], cS[rr][3]);
            *(float4*)(Cb + (size_t)row*N_ + col0 + tx*4) = v;
        }
    } else if (MODE == 1) {
        float* Cb = g_Km + (size_t)b*MN_;
        const float* t1b = g_t1 + b*M_;
        const float* t2b = g_t2 + b*N_;
        float t20 = t2b[col0+tx*4+0], t21 = t2b[col0+tx*4+1];
        float t22 = t2b[col0+tx*4+2], t23 = t2b[col0+tx*4+3];
        #pragma unroll
        for (int rr = 0; rr < 4; rr++) {
            int row = row0 + ty*4 + rr;
            float t1v = t1b[row];
            float4 v;
            v.x = __expf((2.0f*cS[rr][0] - t1v - t20) * EPSI);
            v.y = __expf((2.0f*cS[rr][1] - t1v - t21) * EPSI);
            v.z = __expf((2.0f*cS[rr][2] - t1v - t22) * EPSI);
            v.w = __expf((2.0f*cS[rr][3] - t1v - t23) * EPSI);
            *(float4*)(Cb + (size_t)row*N_ + col0 + tx*4) = v;
        }
    } else {
        const float* Tb = g_T + (size_t)b*MN_;
        float local = 0.f;
        #pragma unroll
        for (int rr = 0; rr < 4; rr++) {
            int row = row0 + ty*4 + rr;
            float4 tv = *(const float4*)(Tb + (size_t)row*N_ + col0 + tx*4);
            local += cS[rr][0]*tv.x + cS[rr][1]*tv.y + cS[rr][2]*tv.z + cS[rr][3]*tv.w;
        }
        red[tid] = local;
        __syncthreads();
        if (tid < 128) red[tid] += red[tid + 128] + red[tid + 256];
        __syncthreads();
        for (int st = 64; st; st >>= 1) {
            if (tid < st) red[tid] += red[tid + st];
            __syncthreads();
        }
        if (!tid) g_cp[tile] = red[0];
    }
}

// ---------------- t1 = (D1.^2) @ rm  (warp per row, 12 warps) --------------
__device__ void sqmv_t1(const float* __restrict__ D1, int bid, int wid, int lane) {
    int fi = bid*RPB + wid;
    int b2 = fi >= M_;
    int i  = fi - b2*M_;
    const float4* row = (const float4*)(D1 + ((size_t)b2*M_ + i)*M_);
    const float4* rmb = (const float4*)(g_rm + b2*M_);
    float s = 0.f;
    for (int q = lane; q < 192; q += 32) {
        float4 v  = row[q];
        float4 r4 = rmb[q];
        s += v.x*v.x*r4.x + v.y*v.y*r4.y + v.z*v.z*r4.z + v.w*v.w*r4.w;
    }
    #pragma unroll
    for (int o = 16; o; o >>= 1) s += __shfl_xor_sync(0xffffffffu, s, o);
    if (!lane) g_t1[fi] = s;
}

// ---------------- persistent mega-kernel ----------------
__global__ void __launch_bounds__(NTHR)
gw_kernel(const float* __restrict__ D1, const float* __restrict__ D2,
          float* __restrict__ out, int out_size) {
    __shared__ float sKs[RPB*N_];        // 24 KB K-row cache
    __shared__ float As[2*AS_BUF];
    __shared__ float Bs[2*BS_BUF];
    __shared__ float tS[N_];
    __shared__ float sRed[NTHR];
    __shared__ float sLoc[RPB];

    int bid = blockIdx.x, tid = threadIdx.x;
    int wid = tid >> 5, lane = tid & 31;
    unsigned gen = 0;
    int bb = bid >> 6;                          // batch (64 blocks each)
    int lid6 = bid & 63;
    unsigned* ctr = &g_bar[bb*32];
    size_t rowbase = (size_t)bid * (RPB*N_);

    // ---------- Phase I: init P, rm, t2, csum[0] ----------
    for (int idx = tid; idx < RPB*N_; idx += NTHR) g_P[rowbase + idx] = AW*BW;
    if (tid < RPB) g_rm[bid*RPB + tid] = AW;
    if (wid < 8) {
        int gw2 = bid*8 + wid;
        int b2 = gw2 >> 9, j = gw2 & 511;
        const float4* row = (const float4*)(D2 + ((size_t)b2*N_ + j)*N_);
        float s = 0.f;
        for (int q = lane; q < 128; q += 32) {
            float4 v = row[q];
            s += v.x*v.x + v.y*v.y + v.z*v.z + v.w*v.w;
        }
        #pragma unroll
        for (int o = 16; o; o >>= 1) s += __shfl_xor_sync(0xffffffffu, s, o);
        if (!lane) g_t2[gw2] = BW * s;
    }
    if (lid6 == 0)
        for (int idx = tid; idx < N_; idx += NTHR) g_csum[0][bb*N_ + idx] = 0.f;
    gsync(gen, ctr);

    int git = 0;
    for (int outer = 0; outer < 10; outer++) {
        // Phase A: T = P@D2 (1 tile/block) + t1 sqmv
        gemm_tile<0>(bid, D1, D2, As, Bs, sRed);
        sqmv_t1(D1, bid, wid, lane);
        gsync(gen, ctr);

        // Phase B: Km = exp(...)
        gemm_tile<1>(bid, D1, D2, As, Bs, sRed);
        gsync(gen, ctr);

        // Sinkhorn: 20 iterations, 1 barrier each
        for (int it = 0; it < 20; it++, git++) {
            if (it == 0) {
                const float4* src = (const float4*)(g_Km + rowbase);
                float4* dst = (float4*)sKs;
                for (int idx = tid; idx < RPB*N_/4; idx += NTHR) dst[idx] = src[idx];
                __syncthreads();
            }
            // u-dot: warp wid handles row wid
            {
                float s = 0.f;
                if (it == 0) {
                    for (int q = lane; q < 128; q += 32) {
                        float4 v = *(const float4*)&sKs[wid*N_ + q*4];
                        s += v.x + v.y + v.z + v.w;
                    }
                } else {
                    for (int q = lane; q < 128; q += 32) {
                        float4 v  = *(const float4*)&sKs[wid*N_ + q*4];
                        float4 t4 = *(const float4*)&tS[q*4];
                        s += v.x*t4.x + v.y*t4.y + v.z*t4.z + v.w*t4.w;
                    }
                }
                #pragma unroll
                for (int o = 16; o; o >>= 1) s += __shfl_xor_sync(0xffffffffu, s, o);
                if (!lane) sLoc[wid] = __fdividef(AW, s);
            }
            __syncthreads();
            // column partials (float4 per thread, tid<128) -> ONE red.v4 each
            {
                int p = git % 3;
                if (tid < 128) {
                    float ax = 0.f, ay = 0.f, az = 0.f, aw = 0.f;
                    #pragma unroll
                    for (int rr = 0; rr < RPB; rr++) {
                        float4 v = *(const float4*)&sKs[rr*N_ + tid*4];
                        float sv = sLoc[rr];
                        ax += v.x*sv; ay += v.y*sv; az += v.z*sv; aw += v.w*sv;
                    }
                    asm volatile("red.global.add.v4.f32 [%0], {%1,%2,%3,%4};"
                                 :: "l"(&g_csum[p][bb*N_ + tid*4]),
                                    "f"(ax), "f"(ay), "f"(az), "f"(aw) : "memory");
                }
                int pn = (p + 1 == 3) ? 0 : p + 1;
                if (tid >= 128 && tid < 136)
                    g_csum[pn][bb*N_ + lid6*8 + (tid - 128)] = 0.f;
            }
            gsync(gen, ctr);
            // t recompute (vectorized, 128 threads)
            {
                int p = git % 3;
                if (tid < 128) {
                    float4 c = *(const float4*)&g_csum[p][bb*N_ + tid*4];
                    float4 t4;
                    t4.x = __fdividef(BW, c.x);
                    t4.y = __fdividef(BW, c.y);
                    t4.z = __fdividef(BW, c.z);
                    t4.w = __fdividef(BW, c.w);
                    *(float4*)&tS[tid*4] = t4;
                }
            }
            __syncthreads();
        }

        // P update + row masses (warp per row)
        {
            float s = 0.f;
            for (int q = lane; q < 128; q += 32) {
                float4 v  = *(const float4*)&sKs[wid*N_ + q*4];
                float4 t4 = *(const float4*)&tS[q*4];
                s += v.x*t4.x + v.y*t4.y + v.z*t4.z + v.w*t4.w;
            }
            #pragma unroll
            for (int o = 16; o; o >>= 1) s += __shfl_xor_sync(0xffffffffu, s, o);
            if (!lane) g_rm[bid*RPB + wid] = sLoc[wid] * s;
        }
        for (int c = tid; c < RPB*N_; c += NTHR) {
            int rr = c >> 9, j = c & 511;
            g_P[rowbase + c] = sLoc[rr] * sKs[c] * tS[j];
        }
        gsync(gen, ctr);
    }

    // ---------- Final cost ----------
    gemm_tile<0>(bid, D1, D2, As, Bs, sRed);
    sqmv_t1(D1, bid, wid, lane);
    gsync(gen, ctr);

    gemm_tile<2>(bid, D1, D2, As, Bs, sRed);
    __syncthreads();
    if (lid6 == 0) {                       // blocks 0, 64: rm . t1
        float s = 0.f;
        for (int i = tid; i < M_; i += NTHR) s += g_rm[bb*M_ + i] * g_t1[bb*M_ + i];
        sRed[tid] = s;
        __syncthreads();
        if (tid < 128) sRed[tid] += sRed[tid + 128] + sRed[tid + 256];
        __syncthreads();
        for (int st = 64; st; st >>= 1) {
            if (tid < st) sRed[tid] += sRed[tid + st];
            __syncthreads();
        }
        if (!tid) g_acc[bb] = sRed[0];
    } else if (lid6 == 1) {                // blocks 1, 65: BW * sum t2
        float s = 0.f;
        for (int j = tid; j < N_; j += NTHR) s += g_t2[bb*N_ + j];
        sRed[tid] = s;
        __syncthreads();
        if (tid < 128) sRed[tid] += sRed[tid + 128] + sRed[tid + 256];
        __syncthreads();
        for (int st = 64; st; st >>= 1) {
            if (tid < st) sRed[tid] += sRed[tid + st];
            __syncthreads();
        }
        if (!tid) g_acc[2 + bb] = BW * sRed[0];
    }
    gsync(gen, ctr);

    // outputs
    if (lid6 == 0 && tid == 0) {
        float cr = 0.f;
        for (int t = 0; t < 64; t++) cr += g_cp[bb*64 + t];
        out[bb] = g_acc[bb] + g_acc[2 + bb] - 2.0f*cr;
    }
    if (out_size > 2) {
        const float2* src = (const float2*)(g_P + rowbase);
        float2* dst = (float2*)(out + 2 + rowbase);
        for (int idx = tid; idx < RPB*N_/2; idx += NTHR) dst[idx] = src[idx];
    }
}

// ---------------- host driver ----------------
extern "C" void kernel_launch(void* const* d_in, const int* in_sizes, int n_in,
                              void* d_out, int out_size) {
    const float* D1 = (const float*)d_in[0];
    const float* D2 = (const float*)d_in[1];
    if (n_in >= 2 && in_sizes[0] == B_*N_*N_ && in_sizes[1] == B_*M_*M_) {
        const float* tmp = D1; D1 = D2; D2 = tmp;
    }
    float* out = (float*)d_out;

    reset_kernel<<<1, 1>>>();
    gw_kernel<<<NBLK, NTHR>>>(D1, D2, out, out_size);
}

// round 10
// speedup vs baseline: 1.1252x; 1.0529x over previous
#include <cuda_runtime.h>

#define NBLK 128
#define NTHR 384
#define B_ 2
#define M_ 768
#define N_ 512
#define MN_ (M_*N_)
#define AW (1.0f/768.0f)
#define BW (1.0f/512.0f)
#define EPSI 20.0f
#define RPB 12            // rows per block: 128*12 = 1536 = B*M
#define AS_STRIDE 100     // 96+4: multiple of 4 floats -> aligned broadcast LDS.128
#define AS_BUF (16*AS_STRIDE)
#define BS_BUF (16*64)

// dynamic smem layout (floats)
#define OFF_KS   0                       // 12*512 = 6144
#define OFF_AS   6144                    // 2*1600 = 3200
#define OFF_BS   (OFF_AS + 2*AS_BUF)     // 2*1024 = 2048
#define OFF_TS   (OFF_BS + 2*BS_BUF)     // 512
#define OFF_RED  (OFF_TS + 512)          // 384
#define OFF_LOC  (OFF_RED + NTHR)        // 12
#define SMEM_FLOATS (OFF_LOC + 16)
#define SMEM_BYTES  (SMEM_FLOATS*4)

typedef unsigned long long ull;

// ---------------- device scratch ----------------
__device__ float g_P [B_*MN_];
__device__ float g_Km[B_*MN_];
__device__ float g_T [B_*MN_];
__device__ float g_rm[B_*M_];
__device__ float g_t1[B_*M_];
__device__ float g_t2[B_*N_];
__device__ float g_csum[3][B_*N_];   // triple-buffered atomic column sums
__device__ float g_cp[128];
__device__ float g_acc[4];
__device__ unsigned g_bar[64];       // [0] batch0 counter, [32] batch1

__global__ void reset_kernel() { g_bar[0] = 0u; g_bar[32] = 0u; }

// ------- per-batch count barrier (R5): release-arrive, acquire-poll --------
__device__ __forceinline__ void gsync(unsigned &gen, unsigned* ctr) {
    ++gen;
    __syncthreads();
    if (threadIdx.x == 0) {
        asm volatile("red.release.gpu.global.add.u32 [%0], %1;"
                     :: "l"(ctr), "r"(1u) : "memory");
        unsigned target = gen * 64u;
        unsigned v;
        do {
            asm volatile("ld.acquire.gpu.global.b32 %0, [%1];"
                         : "=r"(v) : "l"(ctr) : "memory");
        } while (v < target);
    }
    __syncthreads();
}

// ---------------- packed f32x2 helpers ----------------
__device__ __forceinline__ void fma2(ull &d, ull a, ull b) {
    asm("fma.rn.f32x2 %0, %1, %2, %0;" : "+l"(d) : "l"(a), "l"(b));
}
__device__ __forceinline__ ull splat(float x) {
    ull r; asm("mov.b64 %0, {%1, %1};" : "=l"(r) : "f"(x)); return r;
}

// ---------------- GEMM tile 96x64 (128 tiles), 384 thr, micro 8x2 ----------
// Warp = row-group of 8 rows (A reads are single-address broadcast LDS.128),
// lane = column pair (B reads are conflict-free LDS.64). smem/k/warp = 4c,
// matching the 4c fma2 issue budget.
template<int MODE>
__device__ void gemm_tile(int tile, const float* __restrict__ D1,
                          const float* __restrict__ D2,
                          float* As, float* Bs, float* red) {
    const int Kd  = (MODE == 0) ? N_ : M_;
    const int lda = (MODE == 0) ? N_ : M_;
    int b = tile >> 6;
    int r = tile & 63;
    int row0 = (r >> 3) * 96;
    int col0 = (r & 7) * 64;
    const float* A  = (MODE == 0) ? (g_P + (size_t)b*MN_) : (D1 + (size_t)b*M_*M_);
    const float* Bm = (MODE == 0) ? (D2 + (size_t)b*(size_t)N_*N_)
                    : (MODE == 1) ? (g_T + (size_t)b*MN_)
                                  : (g_P + (size_t)b*MN_);
    int tid = threadIdx.x;
    int wid8 = (tid >> 5) * 8;       // warp's 8-row group within tile
    int lane = tid & 31;
    int colp = lane * 2;             // column pair within tile

    // A loader: 384 threads x float4 covers 96x16
    int lr = tid >> 2;
    int lk = (tid & 3) * 4;
    const float* ApL = A + (size_t)(row0 + lr)*lda + lk;
    // B loader: first 256 threads x float4 covers 16x64
    int brow = tid >> 4, bq = tid & 15;
    const float* BpL = Bm + (size_t)brow*N_ + col0 + bq*4;

    ull acc[4][2];                   // 4 row-pairs x 2 cols
    #pragma unroll
    for (int i = 0; i < 4; i++) { acc[i][0] = 0ull; acc[i][1] = 0ull; }

    float4 pa = *(const float4*)(ApL);
    float4 pb;
    if (tid < 256) pb = *(const float4*)(BpL);

    int buf = 0;
    for (int k0 = 0; k0 < Kd; k0 += 16) {
        float* Asb = As + buf*AS_BUF;
        float* Bsb = Bs + buf*BS_BUF;
        Asb[(lk+0)*AS_STRIDE + lr] = pa.x;
        Asb[(lk+1)*AS_STRIDE + lr] = pa.y;
        Asb[(lk+2)*AS_STRIDE + lr] = pa.z;
        Asb[(lk+3)*AS_STRIDE + lr] = pa.w;
        if (tid < 256) *(float4*)&Bsb[brow*64 + bq*4] = pb;
        if (k0 + 16 < Kd) {
            pa = *(const float4*)(ApL + k0 + 16);
            if (tid < 256) pb = *(const float4*)(BpL + (size_t)(k0+16)*N_);
        }
        __syncthreads();
        #pragma unroll
        for (int k = 0; k < 16; k++) {
            const float* ap = Asb + k*AS_STRIDE + wid8;
            ulonglong2 ua0 = *(const ulonglong2*)(ap);      // rows 0-3 (broadcast)
            ulonglong2 ua1 = *(const ulonglong2*)(ap + 4);  // rows 4-7 (broadcast)
            float2 bv = *(const float2*)&Bsb[k*64 + colp];
            ull b0 = splat(bv.x), b1 = splat(bv.y);
            fma2(acc[0][0], ua0.x, b0); fma2(acc[0][1], ua0.x, b1);
            fma2(acc[1][0], ua0.y, b0); fma2(acc[1][1], ua0.y, b1);
            fma2(acc[2][0], ua1.x, b0); fma2(acc[2][1], ua1.x, b1);
            fma2(acc[3][0], ua1.y, b0); fma2(acc[3][1], ua1.y, b1);
        }
        buf ^= 1;
    }

    float cS[8][2];
    #pragma unroll
    for (int p = 0; p < 4; p++)
        #pragma unroll
        for (int j = 0; j < 2; j++) {
            union { ull u; float f[2]; } cv; cv.u = acc[p][j];
            cS[2*p][j]   = cv.f[0];
            cS[2*p+1][j] = cv.f[1];
        }

    if (MODE == 0) {
        float* Cb = g_T + (size_t)b*MN_;
        #pragma unroll
        for (int rr = 0; rr < 8; rr++) {
            int row = row0 + wid8 + rr;
            float2 v = make_float2(cS[rr][0], cS[rr][1]);
            *(float2*)(Cb + (size_t)row*N_ + col0 + colp) = v;
        }
    } else if (MODE == 1) {
        float* Cb = g_Km + (size_t)b*MN_;
        const float* t1b = g_t1 + b*M_;
        const float* t2b = g_t2 + b*N_;
        float t20 = t2b[col0+colp], t21 = t2b[col0+colp+1];
        #pragma unroll
        for (int rr = 0; rr < 8; rr++) {
            int row = row0 + wid8 + rr;
            float t1v = t1b[row];
            float2 v;
            v.x = __expf((2.0f*cS[rr][0] - t1v - t20) * EPSI);
            v.y = __expf((2.0f*cS[rr][1] - t1v - t21) * EPSI);
            *(float2*)(Cb + (size_t)row*N_ + col0 + colp) = v;
        }
    } else {
        const float* Tb = g_T + (size_t)b*MN_;
        float local = 0.f;
        #pragma unroll
        for (int rr = 0; rr < 8; rr++) {
            int row = row0 + wid8 + rr;
            float2 tv = *(const float2*)(Tb + (size_t)row*N_ + col0 + colp);
            local += cS[rr][0]*tv.x + cS[rr][1]*tv.y;
        }
        red[tid] = local;
        __syncthreads();
        if (tid < 128) red[tid] += red[tid + 128] + red[tid + 256];
        __syncthreads();
        for (int st = 64; st; st >>= 1) {
            if (tid < st) red[tid] += red[tid + st];
            __syncthreads();
        }
        if (!tid) g_cp[tile] = red[0];
    }
}

// ---------------- t1 = (D1.^2) @ rm  (warp per row, 12 warps) --------------
__device__ void sqmv_t1(const float* __restrict__ D1, int bid, int wid, int lane) {
    int fi = bid*RPB + wid;
    int b2 = fi >= M_;
    int i  = fi - b2*M_;
    const float4* row = (const float4*)(D1 + ((size_t)b2*M_ + i)*M_);
    const float4* rmb = (const float4*)(g_rm + b2*M_);
    float s = 0.f;
    for (int q = lane; q < 192; q += 32) {
        float4 v  = row[q];
        float4 r4 = rmb[q];
        s += v.x*v.x*r4.x + v.y*v.y*r4.y + v.z*v.z*r4.z + v.w*v.w*r4.w;
    }
    #pragma unroll
    for (int o = 16; o; o >>= 1) s += __shfl_xor_sync(0xffffffffu, s, o);
    if (!lane) g_t1[fi] = s;
}

// ---------------- persistent mega-kernel ----------------
__global__ void __launch_bounds__(NTHR)
gw_kernel(const float* __restrict__ D1, const float* __restrict__ D2,
          float* __restrict__ out, int out_size) {
    extern __shared__ float dyn[];
    float* sKs  = dyn + OFF_KS;
    float* As   = dyn + OFF_AS;
    float* Bs   = dyn + OFF_BS;
    float* tS   = dyn + OFF_TS;
    float* sRed = dyn + OFF_RED;
    float* sLoc = dyn + OFF_LOC;

    int bid = blockIdx.x, tid = threadIdx.x;
    int wid = tid >> 5, lane = tid & 31;
    unsigned gen = 0;
    int bb = bid >> 6;                          // batch (64 blocks each)
    int lid6 = bid & 63;
    unsigned* ctr = &g_bar[bb*32];
    size_t rowbase = (size_t)bid * (RPB*N_);

    // ---------- Phase I: init P, rm, t2, csum[0] ----------
    for (int idx = tid; idx < RPB*N_; idx += NTHR) g_P[rowbase + idx] = AW*BW;
    if (tid < RPB) g_rm[bid*RPB + tid] = AW;
    if (wid < 8) {
        int gw2 = bid*8 + wid;
        int b2 = gw2 >> 9, j = gw2 & 511;
        const float4* row = (const float4*)(D2 + ((size_t)b2*N_ + j)*N_);
        float s = 0.f;
        for (int q = lane; q < 128; q += 32) {
            float4 v = row[q];
            s += v.x*v.x + v.y*v.y + v.z*v.z + v.w*v.w;
        }
        #pragma unroll
        for (int o = 16; o; o >>= 1) s += __shfl_xor_sync(0xffffffffu, s, o);
        if (!lane) g_t2[gw2] = BW * s;
    }
    if (lid6 == 0)
        for (int idx = tid; idx < N_; idx += NTHR) g_csum[0][bb*N_ + idx] = 0.f;
    gsync(gen, ctr);

    int git = 0;
    for (int outer = 0; outer < 10; outer++) {
        // Phase A: T = P@D2 (1 tile/block) + t1 sqmv
        gemm_tile<0>(bid, D1, D2, As, Bs, sRed);
        sqmv_t1(D1, bid, wid, lane);
        gsync(gen, ctr);

        // Phase B: Km = exp(...)
        gemm_tile<1>(bid, D1, D2, As, Bs, sRed);
        gsync(gen, ctr);

        // Sinkhorn: 20 iterations, 1 barrier each (R5 machinery)
        for (int it = 0; it < 20; it++, git++) {
            if (it == 0) {
                const float4* src = (const float4*)(g_Km + rowbase);
                float4* dst = (float4*)sKs;
                for (int idx = tid; idx < RPB*N_/4; idx += NTHR) dst[idx] = src[idx];
                __syncthreads();
            }
            // u-dot: warp wid handles row wid
            {
                float s = 0.f;
                if (it == 0) {
                    for (int q = lane; q < 128; q += 32) {
                        float4 v = *(const float4*)&sKs[wid*N_ + q*4];
                        s += v.x + v.y + v.z + v.w;
                    }
                } else {
                    for (int q = lane; q < 128; q += 32) {
                        float4 v  = *(const float4*)&sKs[wid*N_ + q*4];
                        float4 t4 = *(const float4*)&tS[q*4];
                        s += v.x*t4.x + v.y*t4.y + v.z*t4.z + v.w*t4.w;
                    }
                }
                #pragma unroll
                for (int o = 16; o; o >>= 1) s += __shfl_xor_sync(0xffffffffu, s, o);
                if (!lane) sLoc[wid] = __fdividef(AW, s);
            }
            __syncthreads();
            // column partials -> scalar atomic accumulate; zero next buffer
            {
                int p = git % 3;
                float a0 = 0.f;
                #pragma unroll
                for (int rr = 0; rr < RPB; rr++)
                    a0 += sKs[rr*N_ + tid] * sLoc[rr];
                atomicAdd(&g_csum[p][bb*N_ + tid], a0);
                if (tid < 128) {
                    float a1 = 0.f;
                    #pragma unroll
                    for (int rr = 0; rr < RPB; rr++)
                        a1 += sKs[rr*N_ + tid + 384] * sLoc[rr];
                    atomicAdd(&g_csum[p][bb*N_ + tid + 384], a1);
                }
                int pn = (p + 1 == 3) ? 0 : p + 1;
                if (tid < 8) g_csum[pn][bb*N_ + lid6*8 + tid] = 0.f;
            }
            gsync(gen, ctr);
            // t recompute (redundant per block, into SMEM)
            {
                int p = git % 3;
                tS[tid] = __fdividef(BW, g_csum[p][bb*N_ + tid]);
                if (tid < 128)
                    tS[tid + 384] = __fdividef(BW, g_csum[p][bb*N_ + tid + 384]);
            }
            __syncthreads();
        }

        // P update + row masses (warp per row)
        {
            float s = 0.f;
            for (int q = lane; q < 128; q += 32) {
                float4 v  = *(const float4*)&sKs[wid*N_ + q*4];
                float4 t4 = *(const float4*)&tS[q*4];
                s += v.x*t4.x + v.y*t4.y + v.z*t4.z + v.w*t4.w;
            }
            #pragma unroll
            for (int o = 16; o; o >>= 1) s += __shfl_xor_sync(0xffffffffu, s, o);
            if (!lane) g_rm[bid*RPB + wid] = sLoc[wid] * s;
        }
        for (int c = tid; c < RPB*N_; c += NTHR) {
            int rr = c >> 9, j = c & 511;
            g_P[rowbase + c] = sLoc[rr] * sKs[c] * tS[j];
        }
        gsync(gen, ctr);
    }

    // ---------- Final cost ----------
    gemm_tile<0>(bid, D1, D2, As, Bs, sRed);
    sqmv_t1(D1, bid, wid, lane);
    gsync(gen, ctr);

    gemm_tile<2>(bid, D1, D2, As, Bs, sRed);
    __syncthreads();
    if (lid6 == 0) {                       // blocks 0, 64: rm . t1
        float s = 0.f;
        for (int i = tid; i < M_; i += NTHR) s += g_rm[bb*M_ + i] * g_t1[bb*M_ + i];
        sRed[tid] = s;
        __syncthreads();
        if (tid < 128) sRed[tid] += sRed[tid + 128] + sRed[tid + 256];
        __syncthreads();
        for (int st = 64; st; st >>= 1) {
            if (tid < st) sRed[tid] += sRed[tid + st];
            __syncthreads();
        }
        if (!tid) g_acc[bb] = sRed[0];
    } else if (lid6 == 1) {                // blocks 1, 65: BW * sum t2
        float s = 0.f;
        for (int j = tid; j < N_; j += NTHR) s += g_t2[bb*N_ + j];
        sRed[tid] = s;
        __syncthreads();
        if (tid < 128) sRed[tid] += sRed[tid + 128] + sRed[tid + 256];
        __syncthreads();
        for (int st = 64; st; st >>= 1) {
            if (tid < st) sRed[tid] += sRed[tid + st];
            __syncthreads();
        }
        if (!tid) g_acc[2 + bb] = BW * sRed[0];
    }
    gsync(gen, ctr);

    // outputs
    if (lid6 == 0 && tid == 0) {
        float cr = 0.f;
        for (int t = 0; t < 64; t++) cr += g_cp[bb*64 + t];
        out[bb] = g_acc[bb] + g_acc[2 + bb] - 2.0f*cr;
    }
    if (out_size > 2) {
        const float2* src = (const float2*)(g_P + rowbase);
        float2* dst = (float2*)(out + 2 + rowbase);
        for (int idx = tid; idx < RPB*N_/2; idx += NTHR) dst[idx] = src[idx];
    }
}

// ---------------- host driver ----------------
extern "C" void kernel_launch(void* const* d_in, const int* in_sizes, int n_in,
                              void* d_out, int out_size) {
    const float* D1 = (const float*)d_in[0];
    const float* D2 = (const float*)d_in[1];
    if (n_in >= 2 && in_sizes[0] == B_*N_*N_ && in_sizes[1] == B_*M_*M_) {
        const float* tmp = D1; D1 = D2; D2 = tmp;
    }
    float* out = (float*)d_out;

    static int configured = 0;
    if (!configured) {
        cudaFuncSetAttribute(gw_kernel,
                             cudaFuncAttributeMaxDynamicSharedMemorySize,
                             SMEM_BYTES);
        configured = 1;
    }
    reset_kernel<<<1, 1>>>();
    gw_kernel<<<NBLK, NTHR, SMEM_BYTES>>>(D1, D2, out, out_size);
}